// round 15
// baseline (speedup 1.0000x reference)
#include <cuda_runtime.h>
#include <cuda_fp16.h>
#include <cstdint>
#include <math.h>

// Problem constants
#define PB 8
#define PS 2048
#define PD 1024
#define PC 4096

#define BM 128
#define BN 128

// ===========================================================================
// helpers
// ===========================================================================
__device__ __forceinline__ uint32_t smem_u32(const void* p) {
    uint32_t a;
    asm("{ .reg .u64 t; cvta.to.shared.u64 t, %1; cvt.u32.u64 %0, t; }"
        : "=r"(a) : "l"(p));
    return a;
}

__device__ __forceinline__ void cp16(uint32_t dst, const void* src) {
    asm volatile("cp.async.cg.shared.global [%0], [%1], 16;\n" :: "r"(dst), "l"(src));
}

#define LDMX4(r0, r1, r2, r3, addr) \
    asm volatile("ldmatrix.sync.aligned.m8n8.x4.shared.b16 {%0,%1,%2,%3}, [%4];" \
        : "=r"(r0), "=r"(r1), "=r"(r2), "=r"(r3) : "r"(addr))

#define MMA16816(d, a, b0, b1) \
    asm volatile("mma.sync.aligned.m16n8k16.row.col.f32.f16.f16.f32 " \
        "{%0,%1,%2,%3}, {%4,%5,%6,%7}, {%8,%9}, {%0,%1,%2,%3};" \
        : "+f"((d)[0]), "+f"((d)[1]), "+f"((d)[2]), "+f"((d)[3]) \
        : "r"((a)[0]), "r"((a)[1]), "r"((a)[2]), "r"((a)[3]), "r"(b0), "r"(b1))

#define MBAR_INIT(addr, cnt) \
    asm volatile("mbarrier.init.shared.b64 [%0], %1;" :: "r"((uint32_t)(addr)), "r"((uint32_t)(cnt)) : "memory")

#define MBAR_ARRIVE(addr) \
    asm volatile("mbarrier.arrive.shared.b64 _, [%0];" :: "r"((uint32_t)(addr)) : "memory")

// arrive on mbarrier when all prior cp.asyncs of this thread complete
// (.noinc: arrival counted against the init count)
#define CP_MBAR_ARRIVE(addr) \
    asm volatile("cp.async.mbarrier.arrive.noinc.shared.b64 [%0];" :: "r"((uint32_t)(addr)) : "memory")

#define MBAR_WAIT(mbar_addr, phase) do { \
    uint32_t _mbar = (uint32_t)(mbar_addr); \
    uint32_t _parity = (uint32_t)(phase); \
    uint32_t _done; \
    asm volatile( \
        "{\n\t.reg .pred p;\n\t" \
        "mbarrier.try_wait.parity.acquire.cta.shared::cta.b64 p, [%1], %2;\n\t" \
        "selp.b32 %0, 1, 0, p;\n\t}" \
        : "=r"(_done) : "r"(_mbar), "r"(_parity) : "memory"); \
    if (!_done) { \
        asm volatile( \
            "{\n\t.reg .pred P1;\n\t" \
            "WAIT_LOOP_%=:\n\t" \
            "mbarrier.try_wait.parity.acquire.cta.shared::cta.b64 P1, [%0], %1, 0x989680;\n\t" \
            "@P1 bra.uni WAIT_DONE_%=;\n\t" \
            "bra.uni WAIT_LOOP_%=;\n\t" \
            "WAIT_DONE_%=:\n\t}" \
            :: "r"(_mbar), "r"(_parity) : "memory"); \
    } \
} while(0)

// ===========================================================================
// Scratch (__device__ globals — no runtime allocation)
// ===========================================================================
__device__ __half g_Xh [(size_t)PB * PS * PD];   // X split hi      [B*S, D]
__device__ __half g_Xl [(size_t)PB * PS * PD];   // X split lo
__device__ __half g_Lh [(size_t)PC * PD];        // label split hi  [C, D]
__device__ __half g_Ll [(size_t)PC * PD];
__device__ __half g_XhT[(size_t)PB * PD * PS];   // X^T hi          [B][D, S]
__device__ __half g_AhT[(size_t)PB * PC * PS];   // A^T hi          [B][C, S]
__device__ float2 g_part [(size_t)PB * PS * 64]; // per-(row, 64col-tile) (max, sumexp)
__device__ float2 g_stats[(size_t)PB * PS];      // per-row (max, 1/sum)

// ===========================================================================
// fp32 -> fp16 hi/lo split (lo unscaled; |lo| <= 2^-12|x|)
// ===========================================================================
__global__ void split_kernel(const float* __restrict__ in, __half* __restrict__ ho,
                             __half* __restrict__ lo, int n4) {
    int i = blockIdx.x * blockDim.x + threadIdx.x;
    if (i >= n4) return;
    float4 v = ((const float4*)in)[i];
    __half h0 = __float2half_rn(v.x), h1 = __float2half_rn(v.y);
    __half h2 = __float2half_rn(v.z), h3 = __float2half_rn(v.w);
    __half l0 = __float2half_rn(v.x - __half2float(h0));
    __half l1 = __float2half_rn(v.y - __half2float(h1));
    __half l2 = __float2half_rn(v.z - __half2float(h2));
    __half l3 = __float2half_rn(v.w - __half2float(h3));
    ((__half2*)ho)[2 * i]     = __halves2half2(h0, h1);
    ((__half2*)ho)[2 * i + 1] = __halves2half2(h2, h3);
    ((__half2*)lo)[2 * i]     = __halves2half2(l0, l1);
    ((__half2*)lo)[2 * i + 1] = __halves2half2(l2, l3);
}

// ===========================================================================
// Transposing fp32 -> fp16 (hi only): src [srcRows, srcCols] -> dst [srcCols, srcRows]
// ===========================================================================
__global__ __launch_bounds__(256)
void transpose_h(const float* __restrict__ src, __half* __restrict__ hT,
                 int srcRows, int srcCols, size_t srcBatch, size_t dstBatch) {
    __shared__ float tile[32][65];
    int b = blockIdx.z;
    src += (size_t)b * srcBatch;
    hT  += (size_t)b * dstBatch;
    int c0 = blockIdx.x * 32;
    int r0 = blockIdx.y * 64;
    int t = threadIdx.x;
    int lc = t & 31, lr = t >> 5;
    #pragma unroll
    for (int j = 0; j < 8; ++j)
        tile[lc][lr + 8 * j] = src[(size_t)(r0 + lr + 8 * j) * srcCols + c0 + lc];
    __syncthreads();
    int oc = t >> 3, rp = t & 7;
    #pragma unroll
    for (int j = 0; j < 4; ++j) {
        int rr = (rp + 8 * j) * 2;
        __half h0 = __float2half_rn(tile[oc][rr]);
        __half h1 = __float2half_rn(tile[oc][rr + 1]);
        size_t o = (size_t)(c0 + oc) * srcRows + r0 + rr;
        *(__half2*)(hT + o) = __halves2half2(h0, h1);
    }
}

// ===========================================================================
// Warp-specialized HMMA GEMM (XOR-swizzled smem):
//   320 threads = 8 compute warps (32x64 tiles of 128x128 CTA tile)
//               + 2 producer warps (all cp.async traffic)
//   NT=3: Out = (Ah+Al)*(Bh+Bl)^T via ah*bh + al*bh + ah*bl  (split-fp16)
//   NT=1: Out = Ah*Bh^T
// Ring: STAGES buffers; full[s] mbarrier (count 64, cp.async.noinc arrive),
// empty[s] mbarrier (count 256, consumer arrive). No __syncthreads in loop.
// Consumers double-buffer hi fragments one k16-step ahead.
// ===========================================================================
template<int NT, int BKH, int STAGES, bool STATS>
__global__ __launch_bounds__(320, 1)
void gemm_ws(const __half* __restrict__ Ah, const __half* __restrict__ Al,
             const __half* __restrict__ Bh, const __half* __restrict__ Bl,
             float* __restrict__ Out,
             int lda, int ldb, int ldc, int K,
             size_t aBatch, size_t bBatch, size_t cBatch) {
    constexpr int ROWB  = BKH * 2;             // bytes per smem row
    constexpr int TILEB = 128 * ROWB;          // bytes per operand tile
    constexpr int NOP   = (NT == 3) ? 4 : 2;   // tiles per stage
    constexpr int STB   = NOP * TILEB;         // stage bytes
    constexpr int CPR   = BKH / 8;             // 16B chunks per row
    constexpr int RPASS = 64 / CPR;            // rows per producer pass
    constexpr int SWSH  = (BKH == 32) ? 1 : 0;
    constexpr int SWMK  = CPR - 1;
    constexpr int NKK   = BKH / 16;            // k16 steps per stage

    extern __shared__ char smem[];
    const uint32_t sb = smem_u32(smem);
    const uint32_t mbase = sb + STAGES * STB;  // mbarriers: full[s]@+16s, empty[s]@+16s+8
    const int tid = threadIdx.x;

    const int b = blockIdx.z;
    Ah += (size_t)b * aBatch;
    Bh += (size_t)b * bBatch;
    Out += (size_t)b * cBatch;
    if (NT == 3) { Al += (size_t)b * aBatch; Bl += (size_t)b * bBatch; }

    const int bm = blockIdx.y * BM;
    const int bn = blockIdx.x * BN;
    const int nIter = K / BKH;

    if (tid == 0) {
        #pragma unroll
        for (int s = 0; s < STAGES; ++s) {
            MBAR_INIT(mbase + s * 16, 64);       // full: 64 producer threads
            MBAR_INIT(mbase + s * 16 + 8, 256);  // empty: 256 consumer threads
        }
    }
    __syncthreads();

    if (tid >= 256) {
        // ===================== PRODUCER (warps 8,9) =====================
        const int ptid = tid - 256;
        const int r0p = ptid / CPR;
        const int ck0p = ptid % CPR;
        const int chalv = ck0p * 8;
        const uint32_t sOffP = (uint32_t)r0p * ROWB
                             + (uint32_t)((ck0p ^ ((r0p >> SWSH) & SWMK)) * 16);
        const __half* pAh = Ah + (size_t)(bm + r0p) * lda + chalv;
        const __half* pBh = Bh + (size_t)(bn + r0p) * ldb + chalv;
        const __half* pAl = (NT == 3) ? Al + (size_t)(bm + r0p) * lda + chalv : pAh;
        const __half* pBl = (NT == 3) ? Bl + (size_t)(bn + r0p) * ldb + chalv : pBh;

        for (int t = 0; t < nIter; ++t) {
            const int s = t % STAGES;
            const int r = t / STAGES;
            if (r > 0) MBAR_WAIT(mbase + s * 16 + 8, (r - 1) & 1);
            const uint32_t st = sb + s * STB;
            const size_t ko = (size_t)t * BKH;
            #pragma unroll
            for (int rr = 0; rr < 128; rr += RPASS) {
                const uint32_t so = sOffP + (uint32_t)rr * ROWB;
                cp16(st + 0 * TILEB + so, pAh + (size_t)rr * lda + ko);
                cp16(st + 1 * TILEB + so, pBh + (size_t)rr * ldb + ko);
                if (NT == 3) {
                    cp16(st + 2 * TILEB + so, pAl + (size_t)rr * lda + ko);
                    cp16(st + 3 * TILEB + so, pBl + (size_t)rr * ldb + ko);
                }
            }
            CP_MBAR_ARRIVE(mbase + s * 16);
        }
        return;
    }

    // ======================= CONSUMER (warps 0..7) =======================
    const int lane = tid & 31;
    const int wid = tid >> 5;
    const int warpM = (wid & 3) * 32;
    const int warpN = (wid >> 2) * 64;

    float acc[2][8][4];
    #pragma unroll
    for (int i = 0; i < 2; i++)
        #pragma unroll
        for (int j = 0; j < 8; j++)
            #pragma unroll
            for (int k = 0; k < 4; k++) acc[i][j][k] = 0.0f;

    // ldmatrix address pieces
    const int lr = lane & 15;
    const int lhi = (lane >> 4) & 1;
    const uint32_t lswz = (uint32_t)((lr >> SWSH) & SWMK);
    uint32_t cbv[NKK];
    #pragma unroll
    for (int kk = 0; kk < NKK; ++kk)
        cbv[kk] = (uint32_t)((((kk * 2 + lhi) ^ lswz) << 4));
    uint32_t aRow[2], bRow[4];
    #pragma unroll
    for (int mt = 0; mt < 2; ++mt)
        aRow[mt] = (uint32_t)(warpM + mt * 16 + lr) * ROWB;
    #pragma unroll
    for (int g = 0; g < 4; ++g)
        bRow[g] = (uint32_t)(warpN + g * 16 + lr) * ROWB + 1 * TILEB;

    uint32_t ah2[2][2][4], bh2[2][4][4];

    #define LOAD_HI(bufi, s0a, cb) do {                                        \
        _Pragma("unroll")                                                      \
        for (int mt = 0; mt < 2; ++mt)                                         \
            LDMX4(ah2[bufi][mt][0], ah2[bufi][mt][1],                          \
                  ah2[bufi][mt][2], ah2[bufi][mt][3], (s0a) + aRow[mt] + (cb));\
        _Pragma("unroll")                                                      \
        for (int g = 0; g < 4; ++g)                                            \
            LDMX4(bh2[bufi][g][0], bh2[bufi][g][1],                            \
                  bh2[bufi][g][2], bh2[bufi][g][3], (s0a) + bRow[g] + (cb));   \
    } while (0)

    const int total = nIter * NKK;

    // initial: wait stage 0 full, load hi frags for step 0
    MBAR_WAIT(mbase + 0 * 16, 0);
    LOAD_HI(0, sb, cbv[0]);

    for (int j = 0; j < total; ++j) {
        const int st = j / NKK;
        const int kk = j % NKK;
        const int cbuf = j & 1;
        const uint32_t s0 = sb + (st % STAGES) * STB;

        // prefetch next step's hi fragments
        const int jn = j + 1;
        if (jn < total) {
            const int stn = jn / NKK;
            if ((jn % NKK) == 0)
                MBAR_WAIT(mbase + (stn % STAGES) * 16, (stn / STAGES) & 1);
            LOAD_HI(jn & 1, sb + (stn % STAGES) * STB, cbv[jn % NKK]);
        }

        if (NT == 3) {
            uint32_t al[2][4];
            #pragma unroll
            for (int mt = 0; mt < 2; ++mt)
                LDMX4(al[mt][0], al[mt][1], al[mt][2], al[mt][3],
                      s0 + aRow[mt] + cbv[kk] + 2 * TILEB - 1 * TILEB + 1 * TILEB);
            #pragma unroll
            for (int g = 0; g < 4; ++g) {
                uint32_t bl0, bl1, bl2, bl3;
                LDMX4(bl0, bl1, bl2, bl3, s0 + bRow[g] + cbv[kk] + 2 * TILEB);
                #pragma unroll
                for (int mt = 0; mt < 2; ++mt) {
                    MMA16816(acc[mt][2 * g],     ah2[cbuf][mt], bh2[cbuf][g][0], bh2[cbuf][g][2]);
                    MMA16816(acc[mt][2 * g + 1], ah2[cbuf][mt], bh2[cbuf][g][1], bh2[cbuf][g][3]);
                }
                #pragma unroll
                for (int mt = 0; mt < 2; ++mt) {
                    MMA16816(acc[mt][2 * g],     al[mt], bh2[cbuf][g][0], bh2[cbuf][g][2]);
                    MMA16816(acc[mt][2 * g + 1], al[mt], bh2[cbuf][g][1], bh2[cbuf][g][3]);
                }
                #pragma unroll
                for (int mt = 0; mt < 2; ++mt) {
                    MMA16816(acc[mt][2 * g],     ah2[cbuf][mt], bl0, bl2);
                    MMA16816(acc[mt][2 * g + 1], ah2[cbuf][mt], bl1, bl3);
                }
            }
        } else {
            #pragma unroll
            for (int g = 0; g < 4; ++g) {
                #pragma unroll
                for (int mt = 0; mt < 2; ++mt) {
                    MMA16816(acc[mt][2 * g],     ah2[cbuf][mt], bh2[cbuf][g][0], bh2[cbuf][g][2]);
                    MMA16816(acc[mt][2 * g + 1], ah2[cbuf][mt], bh2[cbuf][g][1], bh2[cbuf][g][3]);
                }
            }
        }

        if (kk == NKK - 1)
            MBAR_ARRIVE(mbase + (st % STAGES) * 16 + 8);
    }
    #undef LOAD_HI

    // ---- softmax partials: per-(row, 64-col warp tile) (max, sumexp) ----
    if (STATS) {
        #pragma unroll
        for (int mt = 0; mt < 2; ++mt) {
            float m0 = -3.4e38f, m1 = -3.4e38f;
            #pragma unroll
            for (int nf = 0; nf < 8; ++nf) {
                m0 = fmaxf(m0, fmaxf(acc[mt][nf][0], acc[mt][nf][1]));
                m1 = fmaxf(m1, fmaxf(acc[mt][nf][2], acc[mt][nf][3]));
            }
            m0 = fmaxf(m0, __shfl_xor_sync(0xFFFFFFFFu, m0, 1));
            m0 = fmaxf(m0, __shfl_xor_sync(0xFFFFFFFFu, m0, 2));
            m1 = fmaxf(m1, __shfl_xor_sync(0xFFFFFFFFu, m1, 1));
            m1 = fmaxf(m1, __shfl_xor_sync(0xFFFFFFFFu, m1, 2));
            float s0 = 0.0f, s1 = 0.0f;
            #pragma unroll
            for (int nf = 0; nf < 8; ++nf) {
                s0 += __expf(acc[mt][nf][0] - m0) + __expf(acc[mt][nf][1] - m0);
                s1 += __expf(acc[mt][nf][2] - m1) + __expf(acc[mt][nf][3] - m1);
            }
            s0 += __shfl_xor_sync(0xFFFFFFFFu, s0, 1);
            s0 += __shfl_xor_sync(0xFFFFFFFFu, s0, 2);
            s1 += __shfl_xor_sync(0xFFFFFFFFu, s1, 1);
            s1 += __shfl_xor_sync(0xFFFFFFFFu, s1, 2);
            if ((lane & 3) == 0) {
                const int row0 = bm + warpM + mt * 16 + (lane >> 2);
                const int pcol = (bn >> 6) + (warpN >> 6);
                g_part[(size_t)row0 * 64 + pcol]       = make_float2(m0, s0);
                g_part[(size_t)(row0 + 8) * 64 + pcol] = make_float2(m1, s1);
            }
        }
    }

    // ---- epilogue: direct fp32 stores (quad-contiguous 32B segments) ----
    #pragma unroll
    for (int mt = 0; mt < 2; ++mt) {
        #pragma unroll
        for (int nf = 0; nf < 8; ++nf) {
            const int row = bm + warpM + mt * 16 + (lane >> 2);
            const int col = bn + warpN + nf * 8 + (lane & 3) * 2;
            *(float2*)&Out[(size_t)row * ldc + col] =
                make_float2(acc[mt][nf][0], acc[mt][nf][1]);
            *(float2*)&Out[(size_t)(row + 8) * ldc + col] =
                make_float2(acc[mt][nf][2], acc[mt][nf][3]);
        }
    }
}

// ---------------------------------------------------------------------------
// Merge 64 per-tile partials per row -> per-row (max, 1/sum). One warp/row.
// ---------------------------------------------------------------------------
__global__ __launch_bounds__(256)
void merge_stats() {
    const int row = blockIdx.x * 8 + (threadIdx.x >> 5);
    const int lane = threadIdx.x & 31;
    float2 p0 = g_part[(size_t)row * 64 + lane];
    float2 p1 = g_part[(size_t)row * 64 + 32 + lane];
    float m = fmaxf(p0.x, p1.x);
    #pragma unroll
    for (int o = 16; o > 0; o >>= 1)
        m = fmaxf(m, __shfl_xor_sync(0xFFFFFFFFu, m, o));
    float s = p0.y * __expf(p0.x - m) + p1.y * __expf(p1.x - m);
    #pragma unroll
    for (int o = 16; o > 0; o >>= 1)
        s += __shfl_xor_sync(0xFFFFFFFFu, s, o);
    if (lane == 0) g_stats[row] = make_float2(m, 1.0f / s);
}

// ---------------------------------------------------------------------------
// Normalize scores -> probs (in place, fp32) AND write fp16 transposed A^T.
// ---------------------------------------------------------------------------
__global__ __launch_bounds__(256)
void norm_transpose(float* __restrict__ A, __half* __restrict__ AhT) {
    __shared__ float tile[32][65];
    __shared__ float2 st[64];
    const int b = blockIdx.z;
    float* Ab = A + (size_t)b * PS * PC;
    __half* hT = AhT + (size_t)b * PC * PS;
    const int c0 = blockIdx.x * 32;
    const int r0 = blockIdx.y * 64;
    const int t = threadIdx.x;
    if (t < 64) st[t] = g_stats[(size_t)b * PS + r0 + t];
    __syncthreads();
    const int lc = t & 31, lr = t >> 5;
    #pragma unroll
    for (int j = 0; j < 8; ++j) {
        const int row = lr + 8 * j;
        const size_t off = (size_t)(r0 + row) * PC + c0 + lc;
        const float2 s = st[row];
        const float p = __expf(Ab[off] - s.x) * s.y;
        tile[lc][row] = p;
        Ab[off] = p;
    }
    __syncthreads();
    const int oc = t >> 3, rp = t & 7;
    #pragma unroll
    for (int j = 0; j < 4; ++j) {
        const int rr = (rp + 8 * j) * 2;
        __half h0 = __float2half_rn(tile[oc][rr]);
        __half h1 = __float2half_rn(tile[oc][rr + 1]);
        const size_t o = (size_t)(c0 + oc) * PS + r0 + rr;
        *(__half2*)(hT + o) = __halves2half2(h0, h1);
    }
}

// ===========================================================================
// Launch.  d_out layout: [output (B*C*D floats) | A (B*S*C floats)]
// ===========================================================================
extern "C" void kernel_launch(void* const* d_in, const int* in_sizes, int n_in,
                              void* d_out, int out_size) {
    const float* x = (const float*)d_in[0];    // [B,S,D]
    const float* lab = (const float*)d_in[1];  // [C,D]
    float* out = (float*)d_out;
    float* Aout = out + (size_t)PB * PC * PD;  // [B*S, C]

    void *pXh, *pXl, *pLh, *pLl, *pXhT, *pAhT;
    cudaGetSymbolAddress(&pXh, g_Xh);   cudaGetSymbolAddress(&pXl, g_Xl);
    cudaGetSymbolAddress(&pLh, g_Lh);   cudaGetSymbolAddress(&pLl, g_Ll);
    cudaGetSymbolAddress(&pXhT, g_XhT); cudaGetSymbolAddress(&pAhT, g_AhT);

    // GEMM1: NT=3, BK=32, 6 stages -> 6*32768 + 128 = 196736 B (1 CTA/SM)
    const int SMEM_G1 = 6 * 4 * 128 * 64 + 128;
    // GEMM2: NT=1, BK=64, 6 stages -> 6*32768 + 128 = 196736 B (1 CTA/SM)
    const int SMEM_G2 = 6 * 2 * 128 * 128 + 128;
    cudaFuncSetAttribute((const void*)gemm_ws<3, 32, 6, true>,
                         cudaFuncAttributeMaxDynamicSharedMemorySize, SMEM_G1);
    cudaFuncSetAttribute((const void*)gemm_ws<1, 64, 6, false>,
                         cudaFuncAttributeMaxDynamicSharedMemorySize, SMEM_G2);

    // 1. fp16 splits of X and L
    split_kernel<<<(PB * PS * PD / 4 + 255) / 256, 256>>>(
        x, (__half*)pXh, (__half*)pXl, PB * PS * PD / 4);
    split_kernel<<<(PC * PD / 4 + 255) / 256, 256>>>(
        lab, (__half*)pLh, (__half*)pLl, PC * PD / 4);

    // 2. X^T (hi only) per batch: [S,D] -> [D,S]
    {
        dim3 g(PD / 32, PS / 64, PB);
        transpose_h<<<g, 256>>>(x, (__half*)pXhT, PS, PD,
                                (size_t)PS * PD, (size_t)PD * PS);
    }

    // 3. GEMM1 (split-fp16, 3 terms + softmax partials): scores[B*S, C] = X @ L^T
    {
        dim3 g(PC / BN, (PB * PS) / BM, 1);
        gemm_ws<3, 32, 6, true><<<g, 320, SMEM_G1>>>(
            (const __half*)pXh, (const __half*)pXl,
            (const __half*)pLh, (const __half*)pLl,
            Aout, PD, PD, PC, PD, 0, 0, 0);
    }

    // 4. merge row partials -> (max, 1/sum)
    merge_stats<<<PB * PS / 8, 256>>>();

    // 5. normalize scores in place + write fp16 A^T
    {
        dim3 g(PC / 32, PS / 64, PB);
        norm_transpose<<<g, 256>>>(Aout, (__half*)pAhT);
    }

    // 6. GEMM2 (pure fp16): out[C, D] = A^T @ X   per batch
    {
        dim3 g(PD / BN, PC / BM, PB);
        gemm_ws<1, 64, 6, false><<<g, 320, SMEM_G2>>>(
            (const __half*)pAhT, (const __half*)pAhT,
            (const __half*)pXhT, (const __half*)pXhT,
            out, PS, PS, PD, PS,
            (size_t)PC * PS, (size_t)PD * PS, (size_t)PC * PD);
    }
}

// round 17
// speedup vs baseline: 1.2498x; 1.2498x over previous
#include <cuda_runtime.h>
#include <cuda_fp16.h>
#include <cstdint>
#include <math.h>

// Problem constants
#define PB 8
#define PS 2048
#define PD 1024
#define PC 4096

#define BM 128
#define BN 128

// ===========================================================================
// helpers
// ===========================================================================
__device__ __forceinline__ uint32_t smem_u32(const void* p) {
    uint32_t a;
    asm("{ .reg .u64 t; cvta.to.shared.u64 t, %1; cvt.u32.u64 %0, t; }"
        : "=r"(a) : "l"(p));
    return a;
}

__device__ __forceinline__ void cp16(uint32_t dst, const void* src) {
    asm volatile("cp.async.cg.shared.global [%0], [%1], 16;\n" :: "r"(dst), "l"(src));
}

#define CP_COMMIT() asm volatile("cp.async.commit_group;\n" ::: "memory")

template<int N>
__device__ __forceinline__ void cp_wait() {
    asm volatile("cp.async.wait_group %0;\n" :: "n"(N) : "memory");
}

#define LDMX4(r0, r1, r2, r3, addr) \
    asm volatile("ldmatrix.sync.aligned.m8n8.x4.shared.b16 {%0,%1,%2,%3}, [%4];" \
        : "=r"(r0), "=r"(r1), "=r"(r2), "=r"(r3) : "r"(addr))

#define MMA16816(d, a, b0, b1) \
    asm volatile("mma.sync.aligned.m16n8k16.row.col.f32.f16.f16.f32 " \
        "{%0,%1,%2,%3}, {%4,%5,%6,%7}, {%8,%9}, {%0,%1,%2,%3};" \
        : "+f"((d)[0]), "+f"((d)[1]), "+f"((d)[2]), "+f"((d)[3]) \
        : "r"((a)[0]), "r"((a)[1]), "r"((a)[2]), "r"((a)[3]), "r"(b0), "r"(b1))

// ===========================================================================
// Scratch (__device__ globals — no runtime allocation)
// ===========================================================================
__device__ __half g_Xh [(size_t)PB * PS * PD];   // X split hi      [B*S, D]
__device__ __half g_Xl [(size_t)PB * PS * PD];   // X split lo
__device__ __half g_Lh [(size_t)PC * PD];        // label split hi  [C, D]
__device__ __half g_Ll [(size_t)PC * PD];
__device__ __half g_XhT[(size_t)PB * PD * PS];   // X^T hi          [B][D, S]
__device__ __half g_AhT[(size_t)PB * PC * PS];   // A^T hi          [B][C, S]
__device__ float2 g_part [(size_t)PB * PS * 64]; // per-(row, 64col-tile) (max, sumexp)
__device__ float2 g_stats[(size_t)PB * PS];      // per-row (max, 1/sum)

// ===========================================================================
// fp32 -> fp16 hi/lo split (lo unscaled; |lo| <= 2^-12|x|)   — for labels
// ===========================================================================
__global__ void split_kernel(const float* __restrict__ in, __half* __restrict__ ho,
                             __half* __restrict__ lo, int n4) {
    int i = blockIdx.x * blockDim.x + threadIdx.x;
    if (i >= n4) return;
    float4 v = ((const float4*)in)[i];
    __half h0 = __float2half_rn(v.x), h1 = __float2half_rn(v.y);
    __half h2 = __float2half_rn(v.z), h3 = __float2half_rn(v.w);
    __half l0 = __float2half_rn(v.x - __half2float(h0));
    __half l1 = __float2half_rn(v.y - __half2float(h1));
    __half l2 = __float2half_rn(v.z - __half2float(h2));
    __half l3 = __float2half_rn(v.w - __half2float(h3));
    ((__half2*)ho)[2 * i]     = __halves2half2(h0, h1);
    ((__half2*)ho)[2 * i + 1] = __halves2half2(h2, h3);
    ((__half2*)lo)[2 * i]     = __halves2half2(l0, l1);
    ((__half2*)lo)[2 * i + 1] = __halves2half2(l2, l3);
}

// ===========================================================================
// Fused X pipeline: one read of x produces Xh, Xl (row-major) AND XhT (hi,
// transposed). Tile 32 cols x 64 rows per block.
// ===========================================================================
__global__ __launch_bounds__(256)
void split_transpose_x(const float* __restrict__ src, __half* __restrict__ ho,
                       __half* __restrict__ lo, __half* __restrict__ hT) {
    __shared__ float tile[32][65];
    const int b = blockIdx.z;
    src += (size_t)b * PS * PD;
    ho  += (size_t)b * PS * PD;
    lo  += (size_t)b * PS * PD;
    hT  += (size_t)b * PD * PS;
    const int c0 = blockIdx.x * 32;
    const int r0 = blockIdx.y * 64;
    const int t = threadIdx.x;
    const int lc = t & 31, lr = t >> 5;
    #pragma unroll
    for (int j = 0; j < 8; ++j) {
        const int row = lr + 8 * j;
        const float v = src[(size_t)(r0 + row) * PD + c0 + lc];
        tile[lc][row] = v;
        const __half h = __float2half_rn(v);
        const __half l = __float2half_rn(v - __half2float(h));
        const size_t o = (size_t)(r0 + row) * PD + c0 + lc;
        ho[o] = h;
        lo[o] = l;
    }
    __syncthreads();
    const int oc = t >> 3, rp = t & 7;
    #pragma unroll
    for (int j = 0; j < 4; ++j) {
        const int rr = (rp + 8 * j) * 2;
        __half h0 = __float2half_rn(tile[oc][rr]);
        __half h1 = __float2half_rn(tile[oc][rr + 1]);
        const size_t o = (size_t)(c0 + oc) * PS + r0 + rr;
        *(__half2*)(hT + o) = __halves2half2(h0, h1);
    }
}

// ===========================================================================
// HMMA GEMM (R13 structure: XOR-swizzled smem, 2 CTAs/SM, 3-stage cp.async,
// one __syncthreads per iter) + R16 additions:
//   * parity-staggered k16 order: odd warps traverse stage steps in reverse,
//     desynchronizing LDSM bursts between the 2 warps sharing each SMSP
//   * running global pointers in the loader (no per-iter 64-bit addr chains)
//   NT=3: Out = (Ah+Al)*(Bh+Bl)^T via ah*bh + al*bh + ah*bl  (split-fp16)
//   NT=1: Out = Ah*Bh^T
// ===========================================================================
template<int NT, int BKH, int STAGES, bool STATS>
__global__ __launch_bounds__(256, 2)
void gemm_hmma(const __half* __restrict__ Ah, const __half* __restrict__ Al,
               const __half* __restrict__ Bh, const __half* __restrict__ Bl,
               float* __restrict__ Out,
               int lda, int ldb, int ldc, int K,
               size_t aBatch, size_t bBatch, size_t cBatch) {
    constexpr int ROWB  = BKH * 2;
    constexpr int TILEB = 128 * ROWB;
    constexpr int NOP   = (NT == 3) ? 4 : 2;
    constexpr int STB   = NOP * TILEB;
    constexpr int CPR   = BKH / 8;
    constexpr int RST   = 256 / CPR;
    constexpr int SWSH  = (BKH == 32) ? 1 : 0;
    constexpr int SWMK  = CPR - 1;
    constexpr int NKK   = BKH / 16;

    extern __shared__ char smem[];
    const uint32_t sb = smem_u32(smem);
    const int tid = threadIdx.x;
    const int lane = tid & 31;
    const int wid = tid >> 5;

    const int b = blockIdx.z;
    Ah += (size_t)b * aBatch;
    Bh += (size_t)b * bBatch;
    Out += (size_t)b * cBatch;
    if (NT == 3) { Al += (size_t)b * aBatch; Bl += (size_t)b * bBatch; }

    const int bm = blockIdx.y * BM;
    const int bn = blockIdx.x * BN;

    // ---- loader mapping ----
    const int r0 = tid / CPR;
    const int ck0 = tid % CPR;
    const int chalves = ck0 * 8;
    const uint32_t swcol = (uint32_t)((ck0 ^ ((r0 >> SWSH) & SWMK)) * 16);
    const uint32_t sOffBase = (uint32_t)r0 * ROWB + swcol;

    // running pointers, advanced by BKH per issued stage
    const __half* qAh = Ah + (size_t)(bm + r0) * lda + chalves;
    const __half* qBh = Bh + (size_t)(bn + r0) * ldb + chalves;
    const __half* qAl = (NT == 3) ? Al + (size_t)(bm + r0) * lda + chalves : qAh;
    const __half* qBl = (NT == 3) ? Bl + (size_t)(bn + r0) * ldb + chalves : qBh;

    const int warpM = (wid & 3) * 32;
    const int warpN = (wid >> 2) * 64;

    float acc[2][8][4];
    #pragma unroll
    for (int i = 0; i < 2; i++)
        #pragma unroll
        for (int j = 0; j < 8; j++)
            #pragma unroll
            for (int k = 0; k < 4; k++) acc[i][j][k] = 0.0f;

    const int nIter = K / BKH;

    #define ISSUE_STAGE(st) do {                                                 \
        _Pragma("unroll")                                                        \
        for (int rr = 0; rr < 128; rr += RST) {                                  \
            const uint32_t so = sOffBase + (uint32_t)rr * ROWB;                  \
            cp16((st) + 0 * TILEB + so, qAh + (size_t)rr * lda);                 \
            if (NT == 3) cp16((st) + 2 * TILEB + so, qAl + (size_t)rr * lda);    \
            cp16((st) + 1 * TILEB + so, qBh + (size_t)rr * ldb);                 \
            if (NT == 3) cp16((st) + 3 * TILEB + so, qBl + (size_t)rr * ldb);    \
        }                                                                        \
        CP_COMMIT();                                                             \
        qAh += BKH; qBh += BKH;                                                  \
        if (NT == 3) { qAl += BKH; qBl += BKH; }                                 \
    } while (0)

    // prologue: stages 0..STAGES-2
    #pragma unroll
    for (int i = 0; i < STAGES - 1; ++i)
        ISSUE_STAGE(sb + i * STB);

    // ldmatrix lane pieces
    const int lr = lane & 15;
    const int lhi = (lane >> 4) & 1;
    const uint32_t lswz = (uint32_t)((lr >> SWSH) & SWMK);
    uint32_t cbv[NKK];
    #pragma unroll
    for (int kk = 0; kk < NKK; ++kk)
        cbv[kk] = (uint32_t)((((kk * 2 + lhi) ^ lswz) << 4));
    const uint32_t lrow = (uint32_t)lr * ROWB;

    int cbuf = 0;
    int ibuf = (STAGES - 1) % STAGES;

    // one k16 step (R13 inner body)
    #define K16_STEP(s0, kk) do {                                                \
        const uint32_t cb = cbv[kk];                                             \
        uint32_t ah[2][4], al[2][4];                                             \
        _Pragma("unroll")                                                        \
        for (int mt = 0; mt < 2; ++mt) {                                         \
            const uint32_t aaddr = (s0) + (uint32_t)(warpM + mt * 16) * ROWB     \
                                   + lrow + cb;                                  \
            LDMX4(ah[mt][0], ah[mt][1], ah[mt][2], ah[mt][3], aaddr);            \
            if (NT == 3)                                                         \
                LDMX4(al[mt][0], al[mt][1], al[mt][2], al[mt][3],                \
                      aaddr + 2 * TILEB);                                        \
        }                                                                        \
        _Pragma("unroll")                                                        \
        for (int g = 0; g < 4; ++g) {                                            \
            const uint32_t baddr = (s0) + (uint32_t)(warpN + g * 16) * ROWB      \
                                   + lrow + cb + 1 * TILEB;                      \
            uint32_t bh0, bh1, bh2, bh3;                                         \
            LDMX4(bh0, bh1, bh2, bh3, baddr);                                    \
            if (NT == 3) {                                                       \
                uint32_t bl0, bl1, bl2, bl3;                                     \
                LDMX4(bl0, bl1, bl2, bl3, baddr + 2 * TILEB);                    \
                _Pragma("unroll")                                                \
                for (int mt = 0; mt < 2; ++mt) {                                 \
                    MMA16816(acc[mt][2 * g],     ah[mt], bh0, bh2);              \
                    MMA16816(acc[mt][2 * g + 1], ah[mt], bh1, bh3);              \
                }                                                                \
                _Pragma("unroll")                                                \
                for (int mt = 0; mt < 2; ++mt) {                                 \
                    MMA16816(acc[mt][2 * g],     ah[mt], bl0, bl2);              \
                    MMA16816(acc[mt][2 * g + 1], ah[mt], bl1, bl3);              \
                }                                                                \
                _Pragma("unroll")                                                \
                for (int mt = 0; mt < 2; ++mt) {                                 \
                    MMA16816(acc[mt][2 * g],     al[mt], bh0, bh2);              \
                    MMA16816(acc[mt][2 * g + 1], al[mt], bh1, bh3);              \
                }                                                                \
            } else {                                                             \
                _Pragma("unroll")                                                \
                for (int mt = 0; mt < 2; ++mt) {                                 \
                    MMA16816(acc[mt][2 * g],     ah[mt], bh0, bh2);              \
                    MMA16816(acc[mt][2 * g + 1], ah[mt], bh1, bh3);              \
                }                                                                \
            }                                                                    \
        }                                                                        \
    } while (0)

    for (int t = 0; t < nIter; ++t) {
        cp_wait<STAGES - 2>();
        __syncthreads();

        if (t + STAGES - 1 < nIter) {
            ISSUE_STAGE(sb + ibuf * STB);
        } else {
            CP_COMMIT();        // empty group keeps wait-count invariant
        }
        ibuf = (ibuf + 1 == STAGES) ? 0 : ibuf + 1;

        const uint32_t s0 = sb + cbuf * STB;
        cbuf = (cbuf + 1 == STAGES) ? 0 : cbuf + 1;

        // parity-staggered k16 order: even warps forward, odd warps reverse.
        if ((wid & 1) == 0) {
            #pragma unroll
            for (int i = 0; i < NKK; ++i) K16_STEP(s0, i);
        } else {
            #pragma unroll
            for (int i = NKK - 1; i >= 0; --i) K16_STEP(s0, i);
        }
    }
    #undef K16_STEP
    #undef ISSUE_STAGE

    // ---- softmax partials: per-(row, 64-col warp tile) (max, sumexp) ----
    if (STATS) {
        #pragma unroll
        for (int mt = 0; mt < 2; ++mt) {
            float m0 = -3.4e38f, m1 = -3.4e38f;
            #pragma unroll
            for (int nf = 0; nf < 8; ++nf) {
                m0 = fmaxf(m0, fmaxf(acc[mt][nf][0], acc[mt][nf][1]));
                m1 = fmaxf(m1, fmaxf(acc[mt][nf][2], acc[mt][nf][3]));
            }
            m0 = fmaxf(m0, __shfl_xor_sync(0xFFFFFFFFu, m0, 1));
            m0 = fmaxf(m0, __shfl_xor_sync(0xFFFFFFFFu, m0, 2));
            m1 = fmaxf(m1, __shfl_xor_sync(0xFFFFFFFFu, m1, 1));
            m1 = fmaxf(m1, __shfl_xor_sync(0xFFFFFFFFu, m1, 2));
            float s0 = 0.0f, s1 = 0.0f;
            #pragma unroll
            for (int nf = 0; nf < 8; ++nf) {
                s0 += __expf(acc[mt][nf][0] - m0) + __expf(acc[mt][nf][1] - m0);
                s1 += __expf(acc[mt][nf][2] - m1) + __expf(acc[mt][nf][3] - m1);
            }
            s0 += __shfl_xor_sync(0xFFFFFFFFu, s0, 1);
            s0 += __shfl_xor_sync(0xFFFFFFFFu, s0, 2);
            s1 += __shfl_xor_sync(0xFFFFFFFFu, s1, 1);
            s1 += __shfl_xor_sync(0xFFFFFFFFu, s1, 2);
            if ((lane & 3) == 0) {
                const int row0 = bm + warpM + mt * 16 + (lane >> 2);
                const int pcol = (bn >> 6) + (warpN >> 6);
                g_part[(size_t)row0 * 64 + pcol]       = make_float2(m0, s0);
                g_part[(size_t)(row0 + 8) * 64 + pcol] = make_float2(m1, s1);
            }
        }
    }

    // ---- epilogue: direct fp32 stores ----
    #pragma unroll
    for (int mt = 0; mt < 2; ++mt) {
        #pragma unroll
        for (int nf = 0; nf < 8; ++nf) {
            const int row = bm + warpM + mt * 16 + (lane >> 2);
            const int col = bn + warpN + nf * 8 + (lane & 3) * 2;
            *(float2*)&Out[(size_t)row * ldc + col] =
                make_float2(acc[mt][nf][0], acc[mt][nf][1]);
            *(float2*)&Out[(size_t)(row + 8) * ldc + col] =
                make_float2(acc[mt][nf][2], acc[mt][nf][3]);
        }
    }
}

// ---------------------------------------------------------------------------
// Merge 64 per-tile partials per row -> per-row (max, 1/sum). One warp/row.
// ---------------------------------------------------------------------------
__global__ __launch_bounds__(256)
void merge_stats() {
    const int row = blockIdx.x * 8 + (threadIdx.x >> 5);
    const int lane = threadIdx.x & 31;
    float2 p0 = g_part[(size_t)row * 64 + lane];
    float2 p1 = g_part[(size_t)row * 64 + 32 + lane];
    float m = fmaxf(p0.x, p1.x);
    #pragma unroll
    for (int o = 16; o > 0; o >>= 1)
        m = fmaxf(m, __shfl_xor_sync(0xFFFFFFFFu, m, o));
    float s = p0.y * __expf(p0.x - m) + p1.y * __expf(p1.x - m);
    #pragma unroll
    for (int o = 16; o > 0; o >>= 1)
        s += __shfl_xor_sync(0xFFFFFFFFu, s, o);
    if (lane == 0) g_stats[row] = make_float2(m, 1.0f / s);
}

// ---------------------------------------------------------------------------
// Normalize scores -> probs (in place, fp32) AND write fp16 transposed A^T.
// ---------------------------------------------------------------------------
__global__ __launch_bounds__(256)
void norm_transpose(float* __restrict__ A, __half* __restrict__ AhT) {
    __shared__ float tile[32][65];
    __shared__ float2 st[64];
    const int b = blockIdx.z;
    float* Ab = A + (size_t)b * PS * PC;
    __half* hT = AhT + (size_t)b * PC * PS;
    const int c0 = blockIdx.x * 32;
    const int r0 = blockIdx.y * 64;
    const int t = threadIdx.x;
    if (t < 64) st[t] = g_stats[(size_t)b * PS + r0 + t];
    __syncthreads();
    const int lc = t & 31, lr = t >> 5;
    #pragma unroll
    for (int j = 0; j < 8; ++j) {
        const int row = lr + 8 * j;
        const size_t off = (size_t)(r0 + row) * PC + c0 + lc;
        const float2 s = st[row];
        const float p = __expf(Ab[off] - s.x) * s.y;
        tile[lc][row] = p;
        Ab[off] = p;
    }
    __syncthreads();
    const int oc = t >> 3, rp = t & 7;
    #pragma unroll
    for (int j = 0; j < 4; ++j) {
        const int rr = (rp + 8 * j) * 2;
        __half h0 = __float2half_rn(tile[oc][rr]);
        __half h1 = __float2half_rn(tile[oc][rr + 1]);
        const size_t o = (size_t)(c0 + oc) * PS + r0 + rr;
        *(__half2*)(hT + o) = __halves2half2(h0, h1);
    }
}

// ===========================================================================
// Launch.  d_out layout: [output (B*C*D floats) | A (B*S*C floats)]
// ===========================================================================
extern "C" void kernel_launch(void* const* d_in, const int* in_sizes, int n_in,
                              void* d_out, int out_size) {
    const float* x = (const float*)d_in[0];    // [B,S,D]
    const float* lab = (const float*)d_in[1];  // [C,D]
    float* out = (float*)d_out;
    float* Aout = out + (size_t)PB * PC * PD;  // [B*S, C]

    void *pXh, *pXl, *pLh, *pLl, *pXhT, *pAhT;
    cudaGetSymbolAddress(&pXh, g_Xh);   cudaGetSymbolAddress(&pXl, g_Xl);
    cudaGetSymbolAddress(&pLh, g_Lh);   cudaGetSymbolAddress(&pLl, g_Ll);
    cudaGetSymbolAddress(&pXhT, g_XhT); cudaGetSymbolAddress(&pAhT, g_AhT);

    // GEMM1: NT=3, BK=32, 3 stages, swizzled -> 98304 B (2 CTAs/SM)
    const int SMEM_G1 = 3 * 4 * 128 * 64;
    // GEMM2: NT=1, BK=64, 3 stages, swizzled -> 98304 B (2 CTAs/SM)
    const int SMEM_G2 = 3 * 2 * 128 * 128;
    cudaFuncSetAttribute((const void*)gemm_hmma<3, 32, 3, true>,
                         cudaFuncAttributeMaxDynamicSharedMemorySize, SMEM_G1);
    cudaFuncSetAttribute((const void*)gemm_hmma<1, 64, 3, false>,
                         cudaFuncAttributeMaxDynamicSharedMemorySize, SMEM_G2);

    // 1. fused X pipeline: one pass -> Xh, Xl, XhT
    {
        dim3 g(PD / 32, PS / 64, PB);
        split_transpose_x<<<g, 256>>>(x, (__half*)pXh, (__half*)pXl,
                                      (__half*)pXhT);
    }
    // 1b. label split
    split_kernel<<<(PC * PD / 4 + 255) / 256, 256>>>(
        lab, (__half*)pLh, (__half*)pLl, PC * PD / 4);

    // 2. GEMM1 (split-fp16, 3 terms + softmax partials): scores[B*S, C] = X @ L^T
    {
        dim3 g(PC / BN, (PB * PS) / BM, 1);
        gemm_hmma<3, 32, 3, true><<<g, 256, SMEM_G1>>>(
            (const __half*)pXh, (const __half*)pXl,
            (const __half*)pLh, (const __half*)pLl,
            Aout, PD, PD, PC, PD, 0, 0, 0);
    }

    // 3. merge row partials -> (max, 1/sum)
    merge_stats<<<PB * PS / 8, 256>>>();

    // 4. normalize scores in place + write fp16 A^T
    {
        dim3 g(PC / 32, PS / 64, PB);
        norm_transpose<<<g, 256>>>(Aout, (__half*)pAhT);
    }

    // 5. GEMM2 (pure fp16): out[C, D] = A^T @ X   per batch
    {
        dim3 g(PD / BN, PC / BM, PB);
        gemm_hmma<1, 64, 3, false><<<g, 256, SMEM_G2>>>(
            (const __half*)pAhT, (const __half*)pAhT,
            (const __half*)pXhT, (const __half*)pXhT,
            out, PS, PS, PD, PS,
            (size_t)PC * PS, (size_t)PD * PS, (size_t)PC * PD);
    }
}